// round 1
// baseline (speedup 1.0000x reference)
#include <cuda_runtime.h>

#define BMAX 32
#define H 512
#define W 512
#define HW (H*W)
#define RAD 4
#define TW 64
#define TH 16
#define NB 256

// Scratch (device globals — no allocation allowed in kernel_launch)
__device__ float    g_blurred[BMAX * HW];   // 32 MiB
__device__ unsigned g_hist[BMAX * NB];
__device__ int      g_min[BMAX];
__device__ int      g_max[BMAX];
__device__ float    g_thresh[BMAX];

// ---------------------------------------------------------------------------
// 0) per-replay state reset (graph replays re-run this)
// ---------------------------------------------------------------------------
__global__ void init_kernel() {
    int i = blockIdx.x * blockDim.x + threadIdx.x;
    if (i < BMAX * NB) g_hist[i] = 0u;
    if (i < BMAX) { g_min[i] = 0x7f7f7f7f; g_max[i] = 0; }
}

// ---------------------------------------------------------------------------
// 1) thermal + separable Gaussian blur (edge-replicate) + per-image min/max
//    tile: TH x TW output, halo RAD on all sides. 256 threads/block.
// ---------------------------------------------------------------------------
__global__ void blur_kernel(const float* __restrict__ x) {
    const int SW = TW + 2 * RAD;   // 72
    const int SH = TH + 2 * RAD;   // 24
    __shared__ float sh[SH][SW];
    __shared__ float vb[TH][SW];

    const int b   = blockIdx.z;
    const int tx0 = blockIdx.x * TW;
    const int ty0 = blockIdx.y * TH;
    const int tid = threadIdx.x;
    const float* __restrict__ img = x + (size_t)b * 4 * HW;   // channel 0

    // Gaussian weights computed in fp32 to match the reference order
    float k[2 * RAD + 1];
    float s = 0.f;
    #pragma unroll
    for (int i = 0; i < 2 * RAD + 1; i++) {
        float xv = (float)(i - RAD);
        k[i] = expf(-0.5f * xv * xv);
        s += k[i];
    }
    #pragma unroll
    for (int i = 0; i < 2 * RAD + 1; i++) k[i] /= s;

    // load tile (+halo) with clamped coords, apply thermal transform
    for (int i = tid; i < SH * SW; i += 256) {
        int r = i / SW, c = i % SW;
        int gy = min(max(ty0 + r - RAD, 0), H - 1);
        int gx = min(max(tx0 + c - RAD, 0), W - 1);
        float v = img[gy * W + gx];
        sh[r][c] = fminf(fmaxf(v * 0.5f + 0.5f, 0.f), 1.f);
    }
    __syncthreads();

    // vertical pass
    for (int i = tid; i < TH * SW; i += 256) {
        int r = i / SW, c = i % SW;
        float acc = 0.f;
        #pragma unroll
        for (int d = 0; d < 2 * RAD + 1; d++) acc += k[d] * sh[r + d][c];
        vb[r][c] = acc;
    }
    __syncthreads();

    // horizontal pass + store + local min/max
    float lmin = 1e30f, lmax = -1e30f;
    for (int i = tid; i < TH * TW; i += 256) {
        int r = i / TW, c = i % TW;
        float acc = 0.f;
        #pragma unroll
        for (int d = 0; d < 2 * RAD + 1; d++) acc += k[d] * vb[r][c + d];
        g_blurred[(size_t)b * HW + (size_t)(ty0 + r) * W + (tx0 + c)] = acc;
        lmin = fminf(lmin, acc);
        lmax = fmaxf(lmax, acc);
    }

    // warp-level reduce then one atomic per warp (all values >= 0 -> int order ok)
    #pragma unroll
    for (int o = 16; o > 0; o >>= 1) {
        lmin = fminf(lmin, __shfl_xor_sync(0xffffffffu, lmin, o));
        lmax = fmaxf(lmax, __shfl_xor_sync(0xffffffffu, lmax, o));
    }
    if ((tid & 31) == 0) {
        atomicMin(&g_min[b], __float_as_int(lmin));
        atomicMax(&g_max[b], __float_as_int(lmax));
    }
}

// ---------------------------------------------------------------------------
// 2) 256-bin histogram per image (shared-mem privatized)
// ---------------------------------------------------------------------------
__global__ void hist_kernel() {
    __shared__ unsigned h[NB];
    const int b = blockIdx.y;
    h[threadIdx.x] = 0u;
    __syncthreads();

    const float lo    = __int_as_float(g_min[b]);
    const float hi    = __int_as_float(g_max[b]);
    const float width = (hi - lo) / 256.0f;
    const float wm    = fmaxf(width, 1e-12f);

    const float4* __restrict__ p =
        reinterpret_cast<const float4*>(g_blurred + (size_t)b * HW);
    const int n4 = HW / 4;
    for (int i = blockIdx.x * 256 + threadIdx.x; i < n4; i += gridDim.x * 256) {
        float4 v = p[i];
        int i0 = min(max((int)floorf((v.x - lo) / wm), 0), 255);
        int i1 = min(max((int)floorf((v.y - lo) / wm), 0), 255);
        int i2 = min(max((int)floorf((v.z - lo) / wm), 0), 255);
        int i3 = min(max((int)floorf((v.w - lo) / wm), 0), 255);
        atomicAdd(&h[i0], 1u);
        atomicAdd(&h[i1], 1u);
        atomicAdd(&h[i2], 1u);
        atomicAdd(&h[i3], 1u);
    }
    __syncthreads();
    unsigned c = h[threadIdx.x];
    if (c) atomicAdd(&g_hist[b * NB + threadIdx.x], c);
}

// ---------------------------------------------------------------------------
// 3) Otsu threshold: one block/image; thread 0 serial-scans (matches
//    jnp.cumsum sequential order & first-occurrence argmax).
// ---------------------------------------------------------------------------
__global__ void otsu_kernel() {
    const int b = blockIdx.x;
    __shared__ float counts[NB], w1[NB], w2[NB], cs[NB], rcs[NB];
    const int t = threadIdx.x;
    counts[t] = (float)g_hist[b * NB + t];
    __syncthreads();

    if (t == 0) {
        float lo    = __int_as_float(g_min[b]);
        float hi    = __int_as_float(g_max[b]);
        float width = (hi - lo) / 256.0f;

        float acc = 0.f;
        for (int i = 0; i < NB; i++)      { acc += counts[i];           w1[i] = acc; }
        acc = 0.f;
        for (int i = NB - 1; i >= 0; i--) { acc += counts[i];           w2[i] = acc; }
        acc = 0.f;
        for (int i = 0; i < NB; i++) {
            float c = lo + ((float)i + 0.5f) * width;
            acc += counts[i] * c;  cs[i] = acc;
        }
        acc = 0.f;
        for (int i = NB - 1; i >= 0; i--) {
            float c = lo + ((float)i + 0.5f) * width;
            acc += counts[i] * c;  rcs[i] = acc;
        }

        float best = -1.f; int bi = 0;
        for (int i = 0; i < NB - 1; i++) {
            float m1 = cs[i]      / fmaxf(w1[i],      1e-12f);
            float m2 = rcs[i + 1] / fmaxf(w2[i + 1],  1e-12f);
            float d  = m1 - m2;
            float v  = w1[i] * w2[i + 1] * d * d;
            if (v > best) { best = v; bi = i; }   // first-max like jnp.argmax
        }
        g_thresh[b] = lo + ((float)bi + 0.5f) * width;
    }
}

// ---------------------------------------------------------------------------
// 4) mask + composite, float4-vectorized
// ---------------------------------------------------------------------------
__global__ void final_kernel(const float* __restrict__ x, float* __restrict__ out) {
    const int b = blockIdx.y;
    const int i = blockIdx.x * blockDim.x + threadIdx.x;
    const int n4 = HW / 4;
    if (i >= n4) return;

    const float t = g_thresh[b];
    const float4 v = reinterpret_cast<const float4*>(g_blurred + (size_t)b * HW)[i];
    float a0 = v.x > t ? 1.f : v.x;
    float a1 = v.y > t ? 1.f : v.y;
    float a2 = v.z > t ? 1.f : v.z;
    float a3 = v.w > t ? 1.f : v.w;

    const float4* __restrict__ xin =
        reinterpret_cast<const float4*>(x + (size_t)b * 4 * HW);
    float4* __restrict__ o = reinterpret_cast<float4*>(out + (size_t)b * 3 * HW);

    #pragma unroll
    for (int c = 0; c < 3; c++) {
        float4 r = xin[(size_t)(c + 1) * n4 + i];
        float4 res;
        res.x = fminf(fmaxf(a0 * r.x + (1.f - a0), 0.f), 1.f);
        res.y = fminf(fmaxf(a1 * r.y + (1.f - a1), 0.f), 1.f);
        res.z = fminf(fmaxf(a2 * r.z + (1.f - a2), 0.f), 1.f);
        res.w = fminf(fmaxf(a3 * r.w + (1.f - a3), 0.f), 1.f);
        o[(size_t)c * n4 + i] = res;
    }
}

// ---------------------------------------------------------------------------
extern "C" void kernel_launch(void* const* d_in, const int* in_sizes, int n_in,
                              void* d_out, int out_size) {
    const float* x = (const float*)d_in[0];
    float* out = (float*)d_out;
    int B = in_sizes[0] / (4 * HW);   // 32
    if (B > BMAX) B = BMAX;

    init_kernel<<<(BMAX * NB + 255) / 256, 256>>>();

    dim3 g1(W / TW, H / TH, B);
    blur_kernel<<<g1, 256>>>(x);

    dim3 g2(16, B);
    hist_kernel<<<g2, 256>>>();

    otsu_kernel<<<B, 256>>>();

    dim3 g4((HW / 4 + 255) / 256, B);
    final_kernel<<<g4, 256>>>(x, out);
}

// round 3
// speedup vs baseline: 1.3150x; 1.3150x over previous
#include <cuda_runtime.h>

#define BMAX 32
#define H 512
#define W 512
#define HW (H*W)
#define RAD 4
#define TW 64
#define TH 16
#define NB 256
#define HIST_BLOCKS 16

// Scratch (device globals — static init only; no runtime allocation)
__device__ float    g_blurred[BMAX * HW];        // 32 MiB
__device__ unsigned g_hist[BMAX * NB];           // zero-init
#define S8 0x7f7f7f7f,0x7f7f7f7f,0x7f7f7f7f,0x7f7f7f7f,0x7f7f7f7f,0x7f7f7f7f,0x7f7f7f7f,0x7f7f7f7f
__device__ int      g_min[BMAX] = {S8, S8, S8, S8};  // +big sentinel (first run)
__device__ int      g_max[BMAX];                     // zero-init (values >= 0)
__device__ unsigned g_done[BMAX];                    // zero-init
__device__ float    g_thresh[BMAX];

// ---------------------------------------------------------------------------
// 1) thermal + separable Gaussian blur (edge-replicate) + per-image min/max
// ---------------------------------------------------------------------------
__global__ void blur_kernel(const float* __restrict__ x) {
    const int SW = TW + 2 * RAD;   // 72
    const int SH = TH + 2 * RAD;   // 24
    __shared__ float sh[SH][SW];
    __shared__ float vb[TH][SW];

    const int b   = blockIdx.z;
    const int tx0 = blockIdx.x * TW;
    const int ty0 = blockIdx.y * TH;
    const int tid = threadIdx.x;
    const float* __restrict__ img = x + (size_t)b * 4 * HW;   // channel 0

    float k[2 * RAD + 1];
    float s = 0.f;
    #pragma unroll
    for (int i = 0; i < 2 * RAD + 1; i++) {
        float xv = (float)(i - RAD);
        k[i] = expf(-0.5f * xv * xv);
        s += k[i];
    }
    #pragma unroll
    for (int i = 0; i < 2 * RAD + 1; i++) k[i] /= s;

    for (int i = tid; i < SH * SW; i += 256) {
        int r = i / SW, c = i % SW;
        int gy = min(max(ty0 + r - RAD, 0), H - 1);
        int gx = min(max(tx0 + c - RAD, 0), W - 1);
        float v = img[gy * W + gx];
        sh[r][c] = fminf(fmaxf(v * 0.5f + 0.5f, 0.f), 1.f);
    }
    __syncthreads();

    for (int i = tid; i < TH * SW; i += 256) {
        int r = i / SW, c = i % SW;
        float acc = 0.f;
        #pragma unroll
        for (int d = 0; d < 2 * RAD + 1; d++) acc += k[d] * sh[r + d][c];
        vb[r][c] = acc;
    }
    __syncthreads();

    float lmin = 1e30f, lmax = -1e30f;
    for (int i = tid; i < TH * TW; i += 256) {
        int r = i / TW, c = i % TW;
        float acc = 0.f;
        #pragma unroll
        for (int d = 0; d < 2 * RAD + 1; d++) acc += k[d] * vb[r][c + d];
        g_blurred[(size_t)b * HW + (size_t)(ty0 + r) * W + (tx0 + c)] = acc;
        lmin = fminf(lmin, acc);
        lmax = fmaxf(lmax, acc);
    }

    #pragma unroll
    for (int o = 16; o > 0; o >>= 1) {
        lmin = fminf(lmin, __shfl_xor_sync(0xffffffffu, lmin, o));
        lmax = fmaxf(lmax, __shfl_xor_sync(0xffffffffu, lmax, o));
    }
    if ((tid & 31) == 0) {   // values >= 0 -> int compare == float compare
        atomicMin(&g_min[b], __float_as_int(lmin));
        atomicMax(&g_max[b], __float_as_int(lmax));
    }
}

// ---------------------------------------------------------------------------
// 2) histogram (shared privatized) + fused Otsu in the last-finishing block.
//    Integer cumsums are exact in fp32; weighted cumsum scanned in fp64
//    (strictly closer to exact than the reference's fp32 sequential scan).
//    First-index argmax tie-break preserved. Epilogue resets replay state.
// ---------------------------------------------------------------------------
__global__ void hist_otsu_kernel() {
    __shared__ unsigned h[NB];
    __shared__ bool s_last;
    const int b = blockIdx.y;
    const int t = threadIdx.x;
    h[t] = 0u;
    __syncthreads();

    const float lo    = __int_as_float(g_min[b]);
    const float hi    = __int_as_float(g_max[b]);
    const float width = (hi - lo) / 256.0f;
    const float wm    = fmaxf(width, 1e-12f);

    const float4* __restrict__ p =
        reinterpret_cast<const float4*>(g_blurred + (size_t)b * HW);
    const int n4 = HW / 4;
    for (int i = blockIdx.x * 256 + t; i < n4; i += HIST_BLOCKS * 256) {
        float4 v = p[i];
        int i0 = min(max((int)floorf((v.x - lo) / wm), 0), 255);
        int i1 = min(max((int)floorf((v.y - lo) / wm), 0), 255);
        int i2 = min(max((int)floorf((v.z - lo) / wm), 0), 255);
        int i3 = min(max((int)floorf((v.w - lo) / wm), 0), 255);
        atomicAdd(&h[i0], 1u);
        atomicAdd(&h[i1], 1u);
        atomicAdd(&h[i2], 1u);
        atomicAdd(&h[i3], 1u);
    }
    __syncthreads();
    unsigned c = h[t];
    if (c) atomicAdd(&g_hist[b * NB + t], c);

    // ---- last-block election ----
    __threadfence();
    if (t == 0) {
        unsigned old = atomicAdd(&g_done[b], 1u);
        s_last = (old == HIST_BLOCKS - 1);
    }
    __syncthreads();
    if (!s_last) return;
    __threadfence();   // acquire: see all blocks' g_hist additions

    // ---- Otsu (parallel, 256 threads) ----
    const int lane = t & 31, wid = t >> 5;
    __shared__ float  s_wW[8];
    __shared__ double s_wP[8];
    __shared__ unsigned long long s_key[8];

    const float cnt    = (float)g_hist[b * NB + t];
    const float center = lo + ((float)t + 0.5f) * width;
    double cp = (double)(cnt * center);   // product rounded in fp32, like ref
    float  w  = cnt;

    #pragma unroll
    for (int o = 1; o < 32; o <<= 1) {
        float  wv = __shfl_up_sync(0xffffffffu, w,  o);
        double pv = __shfl_up_sync(0xffffffffu, cp, o);
        if (lane >= o) { w += wv; cp += pv; }
    }
    if (lane == 31) { s_wW[wid] = w; s_wP[wid] = cp; }
    __syncthreads();

    float offW = 0.f; double offP = 0.0;
    float totW = 0.f; double totP = 0.0;
    #pragma unroll
    for (int i = 0; i < 8; i++) {
        if (i < wid) { offW += s_wW[i]; offP += s_wP[i]; }
        totW += s_wW[i]; totP += s_wP[i];
    }
    const float  w1 = w  + offW;     // inclusive cumsum of counts (exact)
    const double cs = cp + offP;

    unsigned long long key = 0ull;
    if (t < NB - 1) {
        float w2n = totW - w1;                           // w2[t+1] (exact)
        float m1  = (float)cs          / fmaxf(w1,  1e-12f);
        float m2  = (float)(totP - cs) / fmaxf(w2n, 1e-12f);
        float d   = m1 - m2;
        float var = w1 * w2n * d * d;                    // >= 0
        key = ((unsigned long long)__float_as_uint(var) << 8)
              | (unsigned long long)(255 - t);           // first-max tie-break
    }
    #pragma unroll
    for (int o = 16; o > 0; o >>= 1) {
        unsigned long long k2 = __shfl_xor_sync(0xffffffffu, key, o);
        key = (k2 > key) ? k2 : key;
    }
    if (lane == 0) s_key[wid] = key;
    __syncthreads();
    if (t == 0) {
        unsigned long long best = s_key[0];
        #pragma unroll
        for (int i = 1; i < 8; i++) best = (s_key[i] > best) ? s_key[i] : best;
        int bi = 255 - (int)(best & 0xffull);
        g_thresh[b] = lo + ((float)bi + 0.5f) * width;
    }
    __syncthreads();                     // all reads of g_hist done
    g_hist[b * NB + t] = 0u;             // reset for next replay
    if (t == 0) { g_min[b] = 0x7f7f7f7f; g_max[b] = 0; g_done[b] = 0u; }
}

// ---------------------------------------------------------------------------
// 3) mask + composite, float4-vectorized
// ---------------------------------------------------------------------------
__global__ void final_kernel(const float* __restrict__ x, float* __restrict__ out) {
    const int b = blockIdx.y;
    const int i = blockIdx.x * blockDim.x + threadIdx.x;
    const int n4 = HW / 4;
    if (i >= n4) return;

    const float t = g_thresh[b];
    const float4 v = reinterpret_cast<const float4*>(g_blurred + (size_t)b * HW)[i];
    float a0 = v.x > t ? 1.f : v.x;
    float a1 = v.y > t ? 1.f : v.y;
    float a2 = v.z > t ? 1.f : v.z;
    float a3 = v.w > t ? 1.f : v.w;

    const float4* __restrict__ xin =
        reinterpret_cast<const float4*>(x + (size_t)b * 4 * HW);
    float4* __restrict__ o = reinterpret_cast<float4*>(out + (size_t)b * 3 * HW);

    #pragma unroll
    for (int c = 0; c < 3; c++) {
        float4 r = xin[(size_t)(c + 1) * n4 + i];
        float4 res;
        res.x = fminf(fmaxf(a0 * r.x + (1.f - a0), 0.f), 1.f);
        res.y = fminf(fmaxf(a1 * r.y + (1.f - a1), 0.f), 1.f);
        res.z = fminf(fmaxf(a2 * r.z + (1.f - a2), 0.f), 1.f);
        res.w = fminf(fmaxf(a3 * r.w + (1.f - a3), 0.f), 1.f);
        o[(size_t)c * n4 + i] = res;
    }
}

// ---------------------------------------------------------------------------
extern "C" void kernel_launch(void* const* d_in, const int* in_sizes, int n_in,
                              void* d_out, int out_size) {
    const float* x = (const float*)d_in[0];
    float* out = (float*)d_out;
    int B = in_sizes[0] / (4 * HW);   // 32
    if (B > BMAX) B = BMAX;

    dim3 g1(W / TW, H / TH, B);
    blur_kernel<<<g1, 256>>>(x);

    dim3 g2(HIST_BLOCKS, B);
    hist_otsu_kernel<<<g2, 256>>>();

    dim3 g4((HW / 4 + 255) / 256, B);
    final_kernel<<<g4, 256>>>(x, out);
}

// round 4
// speedup vs baseline: 1.9223x; 1.4619x over previous
#include <cuda_runtime.h>

#define BMAX 32
#define H 512
#define W 512
#define HW (H*W)
#define NB 256
#define HIST_BLOCKS 16

#define TW 256     // blur output tile width
#define TH 32      // blur tile height
#define VC 66      // vtile float4 columns (64 main + 2 halo)

// Scratch (device globals — static init only; no runtime allocation)
__device__ float    g_blurred[BMAX * HW];        // 32 MiB
__device__ unsigned g_hist[BMAX * NB];           // zero-init
#define S8 0x7f7f7f7f,0x7f7f7f7f,0x7f7f7f7f,0x7f7f7f7f,0x7f7f7f7f,0x7f7f7f7f,0x7f7f7f7f,0x7f7f7f7f
__device__ int      g_min[BMAX] = {S8, S8, S8, S8};  // +big sentinel (first run)
__device__ int      g_max[BMAX];                     // zero-init (values >= 0)
__device__ unsigned g_done[BMAX];                    // zero-init
__device__ float    g_thresh[BMAX];

__device__ __forceinline__ float thermal(float v) {
    return fminf(fmaxf(v * 0.5f + 0.5f, 0.f), 1.f);
}

// ---------------------------------------------------------------------------
// 1) thermal + separable Gaussian blur (edge-replicate) + per-image min/max.
//    Vertical pass: register ring buffer, 1 LDG.128/row. Horizontal pass:
//    float4-aligned smem reads. Accumulation order (d=0..8, V then H)
//    identical to the previous passing kernel -> bit-identical output.
// ---------------------------------------------------------------------------
__global__ __launch_bounds__(VC * 4) void blur_kernel(const float* __restrict__ x) {
    __shared__ float4 vtile[TH][VC];   // 33,792 B

    const int b       = blockIdx.z;
    const int tile_x0 = blockIdx.x * TW;
    const int tile_y0 = blockIdx.y * TH;
    const int tx      = threadIdx.x;   // 0..65
    const int ty      = threadIdx.y;   // 0..3
    const float4* __restrict__ img4 =
        reinterpret_cast<const float4*>(x + (size_t)b * 4 * HW);   // channel 0

    // Gaussian weights (same construction as before)
    float k[9];
    {
        float s = 0.f;
        #pragma unroll
        for (int i = 0; i < 9; i++) {
            float xv = (float)(i - 4);
            k[i] = expf(-0.5f * xv * xv);
            s += k[i];
        }
        #pragma unroll
        for (int i = 0; i < 9; i++) k[i] /= s;
    }

    // ---- vertical pass: this thread owns vtile float4-column tx ----
    // image float4-column: tx==0 -> left halo, tx==65 -> right halo
    const int  c4        = blockIdx.x * 64 + tx - 1;
    const bool left_oob  = (c4 < 0);          // only when tile_x0==0, tx==0
    const bool right_oob = (c4 > 127);        // only at right image edge
    const int  c4c       = min(max(c4, 0), 127);
    const int  y0        = tile_y0 + ty * 8;  // first of 8 output rows

    float4 ring[9];

    #define LOADROW(DST, Y) do {                                         \
        int yy = min(max((Y), 0), H - 1);                                \
        float4 v = img4[yy * 128 + c4c];                                 \
        v.x = thermal(v.x); v.y = thermal(v.y);                          \
        v.z = thermal(v.z); v.w = thermal(v.w);                          \
        if (left_oob)  { v.y = v.z = v.w = v.x; }                        \
        if (right_oob) { v.x = v.y = v.z = v.w; }                        \
        (DST) = v;                                                       \
    } while (0)

    #pragma unroll
    for (int i = 0; i < 8; i++) LOADROW(ring[i], y0 - 4 + i);

    #pragma unroll
    for (int j = 0; j < 8; j++) {
        LOADROW(ring[(j + 8) % 9], y0 + 4 + j);
        float4 acc = make_float4(0.f, 0.f, 0.f, 0.f);
        #pragma unroll
        for (int d = 0; d < 9; d++) {
            float4 r = ring[(j + d) % 9];
            acc.x += k[d] * r.x;
            acc.y += k[d] * r.y;
            acc.z += k[d] * r.z;
            acc.w += k[d] * r.w;
        }
        vtile[ty * 8 + j][tx] = acc;
    }
    __syncthreads();

    // ---- horizontal pass: 256 of 264 threads, one output float4-col each ----
    const int tid = ty * VC + tx;
    if (tid < 256) {
        const int j4 = tid & 63;    // output float4 column within tile
        const int rg = tid >> 6;    // row group 0..3

        float lmin = 1e30f, lmax = -1e30f;
        float* __restrict__ dst = g_blurred + (size_t)b * HW;

        #pragma unroll
        for (int jr = 0; jr < 8; jr++) {
            const int r = rg * 8 + jr;
            float4 a = vtile[r][j4];
            float4 bq = vtile[r][j4 + 1];
            float4 cq = vtile[r][j4 + 2];
            float w[12] = {a.x, a.y, a.z, a.w, bq.x, bq.y, bq.z, bq.w,
                           cq.x, cq.y, cq.z, cq.w};
            float4 o = make_float4(0.f, 0.f, 0.f, 0.f);
            #pragma unroll
            for (int d = 0; d < 9; d++) {
                o.x += k[d] * w[d];
                o.y += k[d] * w[d + 1];
                o.z += k[d] * w[d + 2];
                o.w += k[d] * w[d + 3];
            }
            reinterpret_cast<float4*>(dst + (size_t)(tile_y0 + r) * W)
                [tile_x0 / 4 + j4] = o;
            lmin = fminf(lmin, fminf(fminf(o.x, o.y), fminf(o.z, o.w)));
            lmax = fmaxf(lmax, fmaxf(fmaxf(o.x, o.y), fmaxf(o.z, o.w)));
        }

        #pragma unroll
        for (int off = 16; off > 0; off >>= 1) {
            lmin = fminf(lmin, __shfl_xor_sync(0xffffffffu, lmin, off));
            lmax = fmaxf(lmax, __shfl_xor_sync(0xffffffffu, lmax, off));
        }
        if ((tid & 31) == 0) {   // values >= 0 -> int compare == float compare
            atomicMin(&g_min[b], __float_as_int(lmin));
            atomicMax(&g_max[b], __float_as_int(lmax));
        }
    }
}

// ---------------------------------------------------------------------------
// 2) histogram (shared privatized) + fused Otsu in the last-finishing block.
// ---------------------------------------------------------------------------
__global__ void hist_otsu_kernel() {
    __shared__ unsigned h[NB];
    __shared__ bool s_last;
    const int b = blockIdx.y;
    const int t = threadIdx.x;
    h[t] = 0u;
    __syncthreads();

    const float lo    = __int_as_float(g_min[b]);
    const float hi    = __int_as_float(g_max[b]);
    const float width = (hi - lo) / 256.0f;
    const float wm    = fmaxf(width, 1e-12f);

    const float4* __restrict__ p =
        reinterpret_cast<const float4*>(g_blurred + (size_t)b * HW);
    const int n4 = HW / 4;
    for (int i = blockIdx.x * 256 + t; i < n4; i += HIST_BLOCKS * 256) {
        float4 v = p[i];
        int i0 = min(max((int)floorf((v.x - lo) / wm), 0), 255);
        int i1 = min(max((int)floorf((v.y - lo) / wm), 0), 255);
        int i2 = min(max((int)floorf((v.z - lo) / wm), 0), 255);
        int i3 = min(max((int)floorf((v.w - lo) / wm), 0), 255);
        atomicAdd(&h[i0], 1u);
        atomicAdd(&h[i1], 1u);
        atomicAdd(&h[i2], 1u);
        atomicAdd(&h[i3], 1u);
    }
    __syncthreads();
    unsigned c = h[t];
    if (c) atomicAdd(&g_hist[b * NB + t], c);

    // ---- last-block election ----
    __threadfence();
    if (t == 0) {
        unsigned old = atomicAdd(&g_done[b], 1u);
        s_last = (old == HIST_BLOCKS - 1);
    }
    __syncthreads();
    if (!s_last) return;
    __threadfence();   // acquire: see all blocks' g_hist additions

    // ---- Otsu (parallel, 256 threads) ----
    const int lane = t & 31, wid = t >> 5;
    __shared__ float  s_wW[8];
    __shared__ double s_wP[8];
    __shared__ unsigned long long s_key[8];

    const float cnt    = (float)g_hist[b * NB + t];
    const float center = lo + ((float)t + 0.5f) * width;
    double cp = (double)(cnt * center);   // product rounded in fp32, like ref
    float  w  = cnt;

    #pragma unroll
    for (int o = 1; o < 32; o <<= 1) {
        float  wv = __shfl_up_sync(0xffffffffu, w,  o);
        double pv = __shfl_up_sync(0xffffffffu, cp, o);
        if (lane >= o) { w += wv; cp += pv; }
    }
    if (lane == 31) { s_wW[wid] = w; s_wP[wid] = cp; }
    __syncthreads();

    float offW = 0.f; double offP = 0.0;
    float totW = 0.f; double totP = 0.0;
    #pragma unroll
    for (int i = 0; i < 8; i++) {
        if (i < wid) { offW += s_wW[i]; offP += s_wP[i]; }
        totW += s_wW[i]; totP += s_wP[i];
    }
    const float  w1 = w  + offW;
    const double cs = cp + offP;

    unsigned long long key = 0ull;
    if (t < NB - 1) {
        float w2n = totW - w1;
        float m1  = (float)cs          / fmaxf(w1,  1e-12f);
        float m2  = (float)(totP - cs) / fmaxf(w2n, 1e-12f);
        float d   = m1 - m2;
        float var = w1 * w2n * d * d;
        key = ((unsigned long long)__float_as_uint(var) << 8)
              | (unsigned long long)(255 - t);
    }
    #pragma unroll
    for (int o = 16; o > 0; o >>= 1) {
        unsigned long long k2 = __shfl_xor_sync(0xffffffffu, key, o);
        key = (k2 > key) ? k2 : key;
    }
    if (lane == 0) s_key[wid] = key;
    __syncthreads();
    if (t == 0) {
        unsigned long long best = s_key[0];
        #pragma unroll
        for (int i = 1; i < 8; i++) best = (s_key[i] > best) ? s_key[i] : best;
        int bi = 255 - (int)(best & 0xffull);
        g_thresh[b] = lo + ((float)bi + 0.5f) * width;
    }
    __syncthreads();
    g_hist[b * NB + t] = 0u;             // reset for next replay
    if (t == 0) { g_min[b] = 0x7f7f7f7f; g_max[b] = 0; g_done[b] = 0u; }
}

// ---------------------------------------------------------------------------
// 3) mask + composite, float4-vectorized
// ---------------------------------------------------------------------------
__global__ void final_kernel(const float* __restrict__ x, float* __restrict__ out) {
    const int b = blockIdx.y;
    const int i = blockIdx.x * blockDim.x + threadIdx.x;
    const int n4 = HW / 4;
    if (i >= n4) return;

    const float t = g_thresh[b];
    const float4 v = reinterpret_cast<const float4*>(g_blurred + (size_t)b * HW)[i];
    float a0 = v.x > t ? 1.f : v.x;
    float a1 = v.y > t ? 1.f : v.y;
    float a2 = v.z > t ? 1.f : v.z;
    float a3 = v.w > t ? 1.f : v.w;

    const float4* __restrict__ xin =
        reinterpret_cast<const float4*>(x + (size_t)b * 4 * HW);
    float4* __restrict__ o = reinterpret_cast<float4*>(out + (size_t)b * 3 * HW);

    #pragma unroll
    for (int c = 0; c < 3; c++) {
        float4 r = xin[(size_t)(c + 1) * n4 + i];
        float4 res;
        res.x = fminf(fmaxf(a0 * r.x + (1.f - a0), 0.f), 1.f);
        res.y = fminf(fmaxf(a1 * r.y + (1.f - a1), 0.f), 1.f);
        res.z = fminf(fmaxf(a2 * r.z + (1.f - a2), 0.f), 1.f);
        res.w = fminf(fmaxf(a3 * r.w + (1.f - a3), 0.f), 1.f);
        o[(size_t)c * n4 + i] = res;
    }
}

// ---------------------------------------------------------------------------
extern "C" void kernel_launch(void* const* d_in, const int* in_sizes, int n_in,
                              void* d_out, int out_size) {
    const float* x = (const float*)d_in[0];
    float* out = (float*)d_out;
    int B = in_sizes[0] / (4 * HW);   // 32
    if (B > BMAX) B = BMAX;

    dim3 t1(VC, 4);
    dim3 g1(W / TW, H / TH, B);
    blur_kernel<<<g1, t1>>>(x);

    dim3 g2(HIST_BLOCKS, B);
    hist_otsu_kernel<<<g2, 256>>>();

    dim3 g4((HW / 4 + 255) / 256, B);
    final_kernel<<<g4, 256>>>(x, out);
}